// round 1
// baseline (speedup 1.0000x reference)
#include <cuda_runtime.h>
#include <math.h>

// Problem constants
#define B_   32
#define CI_  64
#define CO_  64
#define N_   4096
#define M1_  1024     // modes1
#define K2_  2049     // output length N/2+1
#define NPAD 2176     // 17*128 padded columns for GEMM

// ---------------- device global scratch (no runtime alloc allowed) ----------------
__device__ float g_cas4096[4096];
__device__ float g_cos2049[2049];
__device__ float g_sin2049[2049];
__device__ float g_X   [(size_t)2048 * 1024];   // (b*64+i , k)
__device__ float g_G   [(size_t)1024 * 2048];   // (k , b*64+i)
__device__ float g_wT  [(size_t)1024 * 64 * 64];// (k , i , o)
__device__ float g_out2[(size_t)1024 * 2048];   // (k , b*64+o)
__device__ float g_cas2[(size_t)1024 * NPAD];   // (k , n) padded with zeros

// ---------------- 1: small trig tables ----------------
__global__ void k_tables() {
    int t = blockIdx.x * 256 + threadIdx.x;
    if (t < 4096) {
        float s, c;
        sincosf(6.283185307179586f * (float)t / 4096.0f, &s, &c);
        g_cas4096[t] = c + s;
    }
    if (t < 2049) {
        float s, c;
        sincosf(6.283185307179586f * (float)t / 2049.0f, &s, &c);
        g_cos2049[t] = c;
        g_sin2049[t] = s;
    }
}

// ---------------- 2: cas2[k][n] = (cos+sin)(ang_f32(k*n)) / 2049, matching the
// reference's fp32 angle computation via first-order correction ----------------
__global__ void k_cas2() {
    int n = blockIdx.x * 256 + threadIdx.x;
    int k = blockIdx.y;
    if (n >= NPAD) return;
    float v = 0.0f;
    if (n < K2_) {
        int kn = k * n;                          // < 2^22, exact in fp32
        int m  = kn % K2_;
        // reference-style fp32 angle: fl( fl(fl32(2pi)*kn) / 2049 )
        float angf = __fdiv_rn(__fmul_rn(6.283185307179586f, (float)kn), 2049.0f);
        // delta vs true angle (double, no double trig needed)
        double d = (double)angf - (double)kn * (6.283185307179586476925287 / 2049.0);
        float c = g_cos2049[m], s = g_sin2049[m];
        // cas(true + d) ~= cas(true) + d * (cos - sin)
        v = ((c + s) + (float)d * (c - s)) * (1.0f / 2049.0f);
    }
    g_cas2[(size_t)k * NPAD + n] = v;
}

// ---------------- 3: exact recursive_fht via iterative DIT butterflies ----------------
__global__ void k_fht(const float* __restrict__ x) {
    __shared__ float buf[4096];
    __shared__ float tw[2048];
    int row = blockIdx.x;                        // b*64+i
    const float* xr = x + (size_t)row * 4096;
    int tid = threadIdx.x;                       // 256 threads

    for (int v = tid; v < 4096; v += 256) {
        int r = __brev((unsigned)v) >> 20;       // 12-bit bit reversal
        buf[r] = xr[v];
    }
    for (int v = tid; v < 2048; v += 256) tw[v] = g_cas4096[v];
    __syncthreads();

    #pragma unroll 1
    for (int ls = 1; ls <= 12; ls++) {           // stage size s = 1<<ls
        int half  = 1 << (ls - 1);
        int shift = 12 - ls;
        for (int p = tid; p < 2048; p += 256) {
            int j    = p & (half - 1);
            int idx1 = ((p >> (ls - 1)) << ls) | j;
            float t = tw[j << shift];
            float a = buf[idx1];
            float b = buf[idx1 + half];
            buf[idx1]        = fmaf(t, b, a);
            buf[idx1 + half] = fmaf(-t, b, a);
        }
        __syncthreads();
    }
    float* Xr = g_X + (size_t)row * 1024;
    for (int v = tid; v < 1024; v += 256) Xr[v] = buf[v];
}

// ---------------- 4: combine + transpose:  G[k][b*64+i] ----------------
// G = 0.5*(X[b,i] + X[31-b,i] + X[b,63-i] - X[31-b,63-i])
__global__ void k_combine() {
    __shared__ float sa[64][33];
    __shared__ float sb[64][33];
    int k0 = blockIdx.x * 32;
    int b  = blockIdx.y;
    int tid = threadIdx.x;
    int kk = tid & 31, ii = tid >> 5;            // ii in [0,8)
    for (int i = ii; i < 64; i += 8) {
        sa[i][kk] = g_X[(size_t)(b * 64 + i) * 1024 + k0 + kk];
        sb[i][kk] = g_X[(size_t)((31 - b) * 64 + i) * 1024 + k0 + kk];
    }
    __syncthreads();
    int i2 = tid & 63, kq = tid >> 6;            // kq in [0,4)
    for (int kk2 = kq; kk2 < 32; kk2 += 4) {
        float v = 0.5f * (sa[i2][kk2] + sb[i2][kk2] + sa[63 - i2][kk2] - sb[63 - i2][kk2]);
        g_G[(size_t)(k0 + kk2) * 2048 + b * 64 + i2] = v;
    }
}

// ---------------- 5: weights (i,o,k) -> (k,i,o) ----------------
__global__ void k_wtrans(const float* __restrict__ w) {
    __shared__ float t[32][33];
    int k   = blockIdx.x * 32 + threadIdx.x;
    int io0 = blockIdx.y * 32;
    for (int j = threadIdx.y; j < 32; j += 8)
        t[j][threadIdx.x] = w[(size_t)(io0 + j) * 1024 + k];
    __syncthreads();
    int k0 = blockIdx.x * 32;
    for (int j = threadIdx.y; j < 32; j += 8)
        g_wT[(size_t)(k0 + j) * 4096 + io0 + threadIdx.x] = t[threadIdx.x][j];
}

// ---------------- 6: per-k mode mixing: out2[k][b*64+o] = sum_i G[k][b*64+i]*wT[k][i][o] ----
__global__ void k_mix() {
    __shared__ float ws[4096];
    __shared__ float gs[2048];
    int k = blockIdx.x;
    int tid = threadIdx.x;                       // 256
    const float* wk = g_wT + (size_t)k * 4096;
    const float* gk = g_G  + (size_t)k * 2048;
    for (int v = tid; v < 4096; v += 256) ws[v] = wk[v];
    for (int v = tid; v < 2048; v += 256) gs[v] = gk[v];
    __syncthreads();
    int o = tid & 63, bq = tid >> 6;             // bq in [0,4)
    float acc[8];
    #pragma unroll
    for (int r = 0; r < 8; r++) acc[r] = 0.0f;
    #pragma unroll 4
    for (int i = 0; i < 64; i++) {
        float wv = ws[i * 64 + o];
        #pragma unroll
        for (int r = 0; r < 8; r++)
            acc[r] = fmaf(gs[(bq + (r << 2)) * 64 + i], wv, acc[r]);
    }
    float* ok = g_out2 + (size_t)k * 2048;
    #pragma unroll
    for (int r = 0; r < 8; r++) ok[(bq + (r << 2)) * 64 + o] = acc[r];
}

// ---------------- 7: idht GEMM:  C[m][n] = sum_k out2[k][m] * cas2[k][n] ----------------
// M=2048 (b*64+o), N=2049 (padded 2176), K=1024.  128x128x16 tile, 8x8 microtile.
__global__ __launch_bounds__(256) void k_gemm(float* __restrict__ C) {
    __shared__ float As[16][128];
    __shared__ float Bs[16][128];
    int m0 = blockIdx.y * 128;
    int n0 = blockIdx.x * 128;
    int tid = threadIdx.x;
    int tx = tid & 15, ty = tid >> 4;

    float acc[8][8];
    #pragma unroll
    for (int i = 0; i < 8; i++)
        #pragma unroll
        for (int j = 0; j < 8; j++) acc[i][j] = 0.0f;

    for (int k0 = 0; k0 < 1024; k0 += 16) {
        #pragma unroll
        for (int q = tid; q < 512; q += 256) {
            int r = q >> 5, c4 = (q & 31) * 4;
            *(float4*)&As[r][c4] = *(const float4*)&g_out2[(size_t)(k0 + r) * 2048 + m0 + c4];
            *(float4*)&Bs[r][c4] = *(const float4*)&g_cas2[(size_t)(k0 + r) * NPAD + n0 + c4];
        }
        __syncthreads();
        #pragma unroll
        for (int kk = 0; kk < 16; kk++) {
            float ra[8], rb[8];
            *(float4*)&ra[0] = *(float4*)&As[kk][ty * 8];
            *(float4*)&ra[4] = *(float4*)&As[kk][ty * 8 + 4];
            *(float4*)&rb[0] = *(float4*)&Bs[kk][tx * 8];
            *(float4*)&rb[4] = *(float4*)&Bs[kk][tx * 8 + 4];
            #pragma unroll
            for (int i = 0; i < 8; i++)
                #pragma unroll
                for (int j = 0; j < 8; j++)
                    acc[i][j] = fmaf(ra[i], rb[j], acc[i][j]);
        }
        __syncthreads();
    }

    #pragma unroll
    for (int i = 0; i < 8; i++) {
        int m = m0 + ty * 8 + i;
        #pragma unroll
        for (int j = 0; j < 8; j++) {
            int n = n0 + tx * 8 + j;
            if (n < K2_) C[(size_t)m * K2_ + n] = acc[i][j];
        }
    }
}

// ---------------- launch ----------------
extern "C" void kernel_launch(void* const* d_in, const int* in_sizes, int n_in,
                              void* d_out, int out_size) {
    const float* x = (const float*)d_in[0];      // (32,64,4096)
    const float* w = (const float*)d_in[1];      // (64,64,1024)
    float* out = (float*)d_out;                  // (32,64,2049)

    k_tables<<<16, 256>>>();
    k_cas2<<<dim3((NPAD + 255) / 256, 1024), 256>>>();
    k_fht<<<2048, 256>>>(x);
    k_combine<<<dim3(32, 32), 256>>>();
    k_wtrans<<<dim3(32, 128), dim3(32, 8)>>>(w);
    k_mix<<<1024, 256>>>();
    k_gemm<<<dim3(17, 16), 256>>>(out);
}

// round 7
// speedup vs baseline: 1.4354x; 1.4354x over previous
#include <cuda_runtime.h>
#include <cuda_bf16.h>
#include <cstdint>
#include <math.h>

// Problem constants
#define B_   32
#define CI_  64
#define N_   4096
#define K2_  2049     // output length N/2+1
#define NB_  2176     // 17*128 padded B rows

// ---------------- device global scratch ----------------
__device__ float g_cas4096[4096];
__device__ float g_cos2049[2049];
__device__ float g_sin2049[2049];
__device__ float g_X   [(size_t)2048 * 1024];   // (b*64+i , k)
__device__ float g_G   [(size_t)1024 * 2048];   // (k , b*64+i)
__device__ float g_wT  [(size_t)1024 * 4096];   // (k , i , o)
__device__ float g_out2[(size_t)1024 * 2048];   // (k , b*64+o)
__device__ __nv_bfloat16 g_Ahi[(size_t)2048 * 1024];  // (m , k)
__device__ __nv_bfloat16 g_Alo[(size_t)2048 * 1024];
__device__ __nv_bfloat16 g_Bhi[(size_t)NB_  * 1024];  // (n , k)
__device__ __nv_bfloat16 g_Blo[(size_t)NB_  * 1024];

// ---------------- helpers ----------------
__device__ __forceinline__ uint32_t smem_u32(const void* p) {
    uint32_t a;
    asm("{ .reg .u64 t; cvta.to.shared.u64 t, %1; cvt.u32.u64 %0, t; }" : "=r"(a) : "l"(p));
    return a;
}
__device__ __forceinline__ void cp_async16(uint32_t sa, const void* g) {
    asm volatile("cp.async.cg.shared.global [%0], [%1], 16;" :: "r"(sa), "l"(g) : "memory");
}
__device__ __forceinline__ void ldm_x4(uint32_t* r, uint32_t addr) {
    asm volatile("ldmatrix.sync.aligned.m8n8.x4.shared.b16 {%0,%1,%2,%3}, [%4];"
                 : "=r"(r[0]), "=r"(r[1]), "=r"(r[2]), "=r"(r[3]) : "r"(addr));
}
__device__ __forceinline__ void ldm_x2(uint32_t* r, uint32_t addr) {
    asm volatile("ldmatrix.sync.aligned.m8n8.x2.shared.b16 {%0,%1}, [%2];"
                 : "=r"(r[0]), "=r"(r[1]) : "r"(addr));
}
__device__ __forceinline__ void mma16816(float* d, const uint32_t* a, const uint32_t* b) {
    asm volatile(
        "mma.sync.aligned.m16n8k16.row.col.f32.bf16.bf16.f32 "
        "{%0,%1,%2,%3}, {%4,%5,%6,%7}, {%8,%9}, {%0,%1,%2,%3};"
        : "+f"(d[0]), "+f"(d[1]), "+f"(d[2]), "+f"(d[3])
        : "r"(a[0]), "r"(a[1]), "r"(a[2]), "r"(a[3]), "r"(b[0]), "r"(b[1]));
}

// ---------------- 1: small trig tables ----------------
__global__ void k_tables() {
    int t = blockIdx.x * 256 + threadIdx.x;
    if (t < 4096) {
        float s, c;
        sincosf(6.283185307179586f * (float)t / 4096.0f, &s, &c);
        g_cas4096[t] = c + s;
    }
    if (t < 2049) {
        float s, c;
        sincosf(6.283185307179586f * (float)t / 2049.0f, &s, &c);
        g_cos2049[t] = c;
        g_sin2049[t] = s;
    }
}

// ---------------- 2: B[n][k] = cas(ang_f32(k*n))/2049 split into bf16 hi/lo ----------------
__global__ void k_casB() {
    int k = blockIdx.x * 256 + threadIdx.x;      // 4 x 256 = 1024
    int n = blockIdx.y;                          // 0..2175
    float v = 0.0f;
    if (n < K2_) {
        int kn = k * n;                          // < 2^21, exact in fp32
        int m  = kn % K2_;
        float angf = __fdiv_rn(__fmul_rn(6.283185307179586f, (float)kn), 2049.0f);
        double d = (double)angf - (double)kn * (6.283185307179586476925287 / 2049.0);
        float c = g_cos2049[m], s = g_sin2049[m];
        v = ((c + s) + (float)d * (c - s)) * (1.0f / 2049.0f);
    }
    __nv_bfloat16 hi = __float2bfloat16_rn(v);
    __nv_bfloat16 lo = __float2bfloat16_rn(v - __bfloat162float(hi));
    g_Bhi[(size_t)n * 1024 + k] = hi;
    g_Blo[(size_t)n * 1024 + k] = lo;
}

// ---------------- 3: exact recursive_fht via iterative DIT butterflies ----------------
__global__ void k_fht(const float* __restrict__ x) {
    __shared__ float buf[4096];
    __shared__ float tw[2048];
    int row = blockIdx.x;                        // b*64+i
    const float* xr = x + (size_t)row * 4096;
    int tid = threadIdx.x;                       // 256 threads

    for (int v = tid; v < 4096; v += 256) {
        int r = __brev((unsigned)v) >> 20;       // 12-bit bit reversal
        buf[r] = xr[v];
    }
    for (int v = tid; v < 2048; v += 256) tw[v] = g_cas4096[v];
    __syncthreads();

    #pragma unroll 1
    for (int ls = 1; ls <= 12; ls++) {
        int half  = 1 << (ls - 1);
        int shift = 12 - ls;
        for (int p = tid; p < 2048; p += 256) {
            int j    = p & (half - 1);
            int idx1 = ((p >> (ls - 1)) << ls) | j;
            float t = tw[j << shift];
            float a = buf[idx1];
            float b = buf[idx1 + half];
            buf[idx1]        = fmaf(t, b, a);
            buf[idx1 + half] = fmaf(-t, b, a);
        }
        __syncthreads();
    }
    float* Xr = g_X + (size_t)row * 1024;
    for (int v = tid; v < 1024; v += 256) Xr[v] = buf[v];
}

// ---------------- 4: combine + transpose:  G[k][b*64+i] ----------------
__global__ void k_combine() {
    __shared__ float sa[64][33];
    __shared__ float sb[64][33];
    int k0 = blockIdx.x * 32;
    int b  = blockIdx.y;
    int tid = threadIdx.x;
    int kk = tid & 31, ii = tid >> 5;
    for (int i = ii; i < 64; i += 8) {
        sa[i][kk] = g_X[(size_t)(b * 64 + i) * 1024 + k0 + kk];
        sb[i][kk] = g_X[(size_t)((31 - b) * 64 + i) * 1024 + k0 + kk];
    }
    __syncthreads();
    int i2 = tid & 63, kq = tid >> 6;
    for (int kk2 = kq; kk2 < 32; kk2 += 4) {
        float v = 0.5f * (sa[i2][kk2] + sb[i2][kk2] + sa[63 - i2][kk2] - sb[63 - i2][kk2]);
        g_G[(size_t)(k0 + kk2) * 2048 + b * 64 + i2] = v;
    }
}

// ---------------- 5: weights (i,o,k) -> (k,i,o) ----------------
__global__ void k_wtrans(const float* __restrict__ w) {
    __shared__ float t[32][33];
    int k   = blockIdx.x * 32 + threadIdx.x;
    int io0 = blockIdx.y * 32;
    for (int j = threadIdx.y; j < 32; j += 8)
        t[j][threadIdx.x] = w[(size_t)(io0 + j) * 1024 + k];
    __syncthreads();
    int k0 = blockIdx.x * 32;
    for (int j = threadIdx.y; j < 32; j += 8)
        g_wT[(size_t)(k0 + j) * 4096 + io0 + threadIdx.x] = t[threadIdx.x][j];
}

// ---------------- 6: per-k mode mixing ----------------
__global__ void k_mix() {
    __shared__ float ws[4096];
    __shared__ float gs[2048];
    int k = blockIdx.x;
    int tid = threadIdx.x;
    const float* wk = g_wT + (size_t)k * 4096;
    const float* gk = g_G  + (size_t)k * 2048;
    for (int v = tid; v < 4096; v += 256) ws[v] = wk[v];
    for (int v = tid; v < 2048; v += 256) gs[v] = gk[v];
    __syncthreads();
    int o = tid & 63, bq = tid >> 6;
    float acc[8];
    #pragma unroll
    for (int r = 0; r < 8; r++) acc[r] = 0.0f;
    #pragma unroll 4
    for (int i = 0; i < 64; i++) {
        float wv = ws[i * 64 + o];
        #pragma unroll
        for (int r = 0; r < 8; r++)
            acc[r] = fmaf(gs[(bq + (r << 2)) * 64 + i], wv, acc[r]);
    }
    float* ok = g_out2 + (size_t)k * 2048;
    #pragma unroll
    for (int r = 0; r < 8; r++) ok[(bq + (r << 2)) * 64 + o] = acc[r];
}

// ---------------- 7: transpose + split A: out2 (k,m) fp32 -> Ahi/Alo (m,k) bf16 ----------------
__global__ void k_asplit() {
    __shared__ float t[32][33];
    int m0 = blockIdx.x * 32;
    int k0 = blockIdx.y * 32;
    int tx = threadIdx.x, ty = threadIdx.y;      // 32 x 8
    for (int j = ty; j < 32; j += 8)
        t[j][tx] = g_out2[(size_t)(k0 + j) * 2048 + m0 + tx];
    __syncthreads();
    for (int j = ty; j < 32; j += 8) {
        float v = t[tx][j];
        __nv_bfloat16 hi = __float2bfloat16_rn(v);
        __nv_bfloat16 lo = __float2bfloat16_rn(v - __bfloat162float(hi));
        size_t idx = (size_t)(m0 + j) * 1024 + k0 + tx;
        g_Ahi[idx] = hi;
        g_Alo[idx] = lo;
    }
}

// ---------------- 8: HMMA bf16-split GEMM (mma.sync, base sm_103 path) ----------------
// C[m][n] = sum_k (Ahi+Alo)[m][k]*(Bhi+Blo)[n][k], dropping lo*lo.
// 128x128 CTA tile, 8 warps (2x4), warp tile 64x32, K chunks of 32, cp.async 2-stage.
#define KC    32
#define AST   40                     // padded smem row stride (bf16 elems)
#define TILE_BYTES (128 * AST * 2)   // 10240
#define STAGE_BYTES (4 * TILE_BYTES) // 40960
#define HGEMM_SMEM  (2 * STAGE_BYTES)

__global__ __launch_bounds__(256, 1) void k_hgemm(float* __restrict__ C) {
    extern __shared__ __nv_bfloat16 sm[];
    const uint32_t smb = smem_u32(sm);
    const int tid = threadIdx.x;
    const int wid = tid >> 5, lane = tid & 31;
    const int wm = wid >> 2, wn = wid & 3;       // 2 x 4 warp grid
    const int m0 = blockIdx.y * 128, n0 = blockIdx.x * 128;

    const __nv_bfloat16* gb[4] = {
        g_Ahi + (size_t)m0 * 1024, g_Alo + (size_t)m0 * 1024,
        g_Bhi + (size_t)n0 * 1024, g_Blo + (size_t)n0 * 1024 };

    // per-thread load coords: 2 segments per tile per chunk
    const int seg0 = tid, seg1 = tid + 256;
    const int lr0 = seg0 >> 2, lc0 = (seg0 & 3) * 16;   // row, byte col within 64B of chunk
    const int lr1 = seg1 >> 2, lc1 = (seg1 & 3) * 16;

    float acc[4][4][4];
    #pragma unroll
    for (int i = 0; i < 4; i++)
        #pragma unroll
        for (int j = 0; j < 4; j++)
            #pragma unroll
            for (int q = 0; q < 4; q++) acc[i][j][q] = 0.0f;

    // issue chunk c into stage s
    auto issue = [&](int c, int s) {
        uint32_t sbase = smb + (uint32_t)s * STAGE_BYTES;
        size_t gc = (size_t)c * 64;              // byte offset along k
        #pragma unroll
        for (int t = 0; t < 4; t++) {
            const char* g = (const char*)gb[t];
            uint32_t tb = sbase + (uint32_t)t * TILE_BYTES;
            cp_async16(tb + (uint32_t)(lr0 * (AST * 2) + lc0), g + (size_t)lr0 * 2048 + gc + lc0);
            cp_async16(tb + (uint32_t)(lr1 * (AST * 2) + lc1), g + (size_t)lr1 * 2048 + gc + lc1);
        }
        asm volatile("cp.async.commit_group;" ::: "memory");
    };

    issue(0, 0);

    // ldmatrix per-lane offsets (bytes, within a tile)
    const uint32_t a_base = (uint32_t)(((wm * 64 + (lane & 15)) * AST + ((lane >> 4) << 3)) * 2);
    const uint32_t b_base = (uint32_t)(((wn * 32 + (lane & 7)) * AST + (((lane >> 3) & 1) << 3)) * 2);

    for (int c = 0; c < 32; ++c) {
        int s = c & 1;
        if (c + 1 < 32) {
            issue(c + 1, s ^ 1);
            asm volatile("cp.async.wait_group 1;" ::: "memory");
        } else {
            asm volatile("cp.async.wait_group 0;" ::: "memory");
        }
        __syncthreads();

        uint32_t st = smb + (uint32_t)s * STAGE_BYTES;
        #pragma unroll
        for (int kk = 0; kk < 2; ++kk) {         // two k16 steps
            uint32_t ko = (uint32_t)(kk * 32);   // 16 elems * 2B
            uint32_t ahi[4][4], alo[4][4], bhi[4][2], blo[4][2];
            #pragma unroll
            for (int mt = 0; mt < 4; ++mt) {
                uint32_t ao = a_base + ko + (uint32_t)(mt * 16 * AST * 2);
                ldm_x4(ahi[mt], st + ao);
                ldm_x4(alo[mt], st + TILE_BYTES + ao);
            }
            #pragma unroll
            for (int nt = 0; nt < 4; ++nt) {
                uint32_t bo = b_base + ko + (uint32_t)(nt * 8 * AST * 2);
                ldm_x2(bhi[nt], st + 2 * TILE_BYTES + bo);
                ldm_x2(blo[nt], st + 3 * TILE_BYTES + bo);
            }
            #pragma unroll
            for (int mt = 0; mt < 4; ++mt)
                #pragma unroll
                for (int nt = 0; nt < 4; ++nt) {
                    mma16816(acc[mt][nt], ahi[mt], bhi[nt]);
                    mma16816(acc[mt][nt], ahi[mt], blo[nt]);
                    mma16816(acc[mt][nt], alo[mt], bhi[nt]);
                }
        }
        __syncthreads();
    }

    // epilogue: m16n8 f32 fragment mapping
    const int rbase = m0 + wm * 64 + (lane >> 2);
    const int cbase = n0 + wn * 32 + (lane & 3) * 2;
    #pragma unroll
    for (int mt = 0; mt < 4; ++mt) {
        #pragma unroll
        for (int nt = 0; nt < 4; ++nt) {
            int r = rbase + mt * 16;
            int cc = cbase + nt * 8;
            if (cc < K2_)     C[(size_t)r * K2_ + cc]           = acc[mt][nt][0];
            if (cc + 1 < K2_) C[(size_t)r * K2_ + cc + 1]       = acc[mt][nt][1];
            if (cc < K2_)     C[(size_t)(r + 8) * K2_ + cc]     = acc[mt][nt][2];
            if (cc + 1 < K2_) C[(size_t)(r + 8) * K2_ + cc + 1] = acc[mt][nt][3];
        }
    }
}

// ---------------- launch ----------------
extern "C" void kernel_launch(void* const* d_in, const int* in_sizes, int n_in,
                              void* d_out, int out_size) {
    const float* x = (const float*)d_in[0];      // (32,64,4096)
    const float* w = (const float*)d_in[1];      // (64,64,1024)
    float* out = (float*)d_out;                  // (32,64,2049)

    cudaFuncSetAttribute(k_hgemm, cudaFuncAttributeMaxDynamicSharedMemorySize, HGEMM_SMEM);

    k_tables<<<16, 256>>>();
    k_casB<<<dim3(4, NB_), 256>>>();
    k_fht<<<2048, 256>>>(x);
    k_combine<<<dim3(32, 32), 256>>>();
    k_wtrans<<<dim3(32, 128), dim3(32, 8)>>>(w);
    k_mix<<<1024, 256>>>();
    k_asplit<<<dim3(64, 32), dim3(32, 8)>>>();
    k_hgemm<<<dim3(17, 16), 256, HGEMM_SMEM>>>(out);
}

// round 8
// speedup vs baseline: 1.4368x; 1.0010x over previous
#include <cuda_runtime.h>
#include <cuda_bf16.h>
#include <cstdint>
#include <math.h>

// Problem constants
#define B_   32
#define CI_  64
#define N_   4096
#define K2_  2049     // output length N/2+1
#define NB_  2176     // 17*128 padded B rows

// ---------------- device global scratch ----------------
__device__ float g_cas4096[4096];
__device__ float g_cos2049[2049];
__device__ float g_sin2049[2049];
__device__ float g_X   [(size_t)2048 * 1024];   // (b*64+i , k)
__device__ float g_G   [(size_t)1024 * 2048];   // (k , b*64+i)
__device__ float g_wT  [(size_t)1024 * 4096];   // (k , i , o)
__device__ float g_out2[(size_t)1024 * 2048];   // (k , b*64+o)
__device__ __nv_bfloat16 g_Ahi[(size_t)2048 * 1024];  // (m , k)
__device__ __nv_bfloat16 g_Alo[(size_t)2048 * 1024];
__device__ __nv_bfloat16 g_Bhi[(size_t)NB_  * 1024];  // (n , k)
__device__ __nv_bfloat16 g_Blo[(size_t)NB_  * 1024];

// ---------------- helpers ----------------
__device__ __forceinline__ uint32_t smem_u32(const void* p) {
    uint32_t a;
    asm("{ .reg .u64 t; cvta.to.shared.u64 t, %1; cvt.u32.u64 %0, t; }" : "=r"(a) : "l"(p));
    return a;
}
__device__ __forceinline__ void cp_async16(uint32_t sa, const void* g) {
    asm volatile("cp.async.cg.shared.global [%0], [%1], 16;" :: "r"(sa), "l"(g) : "memory");
}
__device__ __forceinline__ void ldm_x4(uint32_t* r, uint32_t addr) {
    asm volatile("ldmatrix.sync.aligned.m8n8.x4.shared.b16 {%0,%1,%2,%3}, [%4];"
                 : "=r"(r[0]), "=r"(r[1]), "=r"(r[2]), "=r"(r[3]) : "r"(addr));
}
__device__ __forceinline__ void ldm_x2(uint32_t* r, uint32_t addr) {
    asm volatile("ldmatrix.sync.aligned.m8n8.x2.shared.b16 {%0,%1}, [%2];"
                 : "=r"(r[0]), "=r"(r[1]) : "r"(addr));
}
__device__ __forceinline__ void mma16816(float* d, const uint32_t* a, const uint32_t* b) {
    asm volatile(
        "mma.sync.aligned.m16n8k16.row.col.f32.bf16.bf16.f32 "
        "{%0,%1,%2,%3}, {%4,%5,%6,%7}, {%8,%9}, {%0,%1,%2,%3};"
        : "+f"(d[0]), "+f"(d[1]), "+f"(d[2]), "+f"(d[3])
        : "r"(a[0]), "r"(a[1]), "r"(a[2]), "r"(a[3]), "r"(b[0]), "r"(b[1]));
}

// ---------------- 1: small trig tables ----------------
__global__ void k_tables() {
    int t = blockIdx.x * 256 + threadIdx.x;
    if (t < 4096) {
        float s, c;
        sincosf(6.283185307179586f * (float)t / 4096.0f, &s, &c);
        g_cas4096[t] = c + s;
    }
    if (t < 2049) {
        float s, c;
        sincosf(6.283185307179586f * (float)t / 2049.0f, &s, &c);
        g_cos2049[t] = c;
        g_sin2049[t] = s;
    }
}

// ---------------- 2: B[n][k] = cas(ang_f32(k*n))/2049 split into bf16 hi/lo ----------------
__global__ void k_casB() {
    int k = blockIdx.x * 256 + threadIdx.x;      // 4 x 256 = 1024
    int n = blockIdx.y;                          // 0..2175
    float v = 0.0f;
    if (n < K2_) {
        int kn = k * n;                          // < 2^21, exact in fp32
        int m  = kn % K2_;
        float angf = __fdiv_rn(__fmul_rn(6.283185307179586f, (float)kn), 2049.0f);
        double d = (double)angf - (double)kn * (6.283185307179586476925287 / 2049.0);
        float c = g_cos2049[m], s = g_sin2049[m];
        v = ((c + s) + (float)d * (c - s)) * (1.0f / 2049.0f);
    }
    __nv_bfloat16 hi = __float2bfloat16_rn(v);
    __nv_bfloat16 lo = __float2bfloat16_rn(v - __bfloat162float(hi));
    g_Bhi[(size_t)n * 1024 + k] = hi;
    g_Blo[(size_t)n * 1024 + k] = lo;
}

// ---------------- 3: exact recursive_fht via iterative DIT butterflies ----------------
__global__ void k_fht(const float* __restrict__ x) {
    __shared__ float buf[4096];
    __shared__ float tw[2048];
    int row = blockIdx.x;                        // b*64+i
    const float* xr = x + (size_t)row * 4096;
    int tid = threadIdx.x;                       // 256 threads

    for (int v = tid; v < 4096; v += 256) {
        int r = __brev((unsigned)v) >> 20;       // 12-bit bit reversal
        buf[r] = xr[v];
    }
    for (int v = tid; v < 2048; v += 256) tw[v] = g_cas4096[v];
    __syncthreads();

    #pragma unroll 1
    for (int ls = 1; ls <= 12; ls++) {
        int half  = 1 << (ls - 1);
        int shift = 12 - ls;
        for (int p = tid; p < 2048; p += 256) {
            int j    = p & (half - 1);
            int idx1 = ((p >> (ls - 1)) << ls) | j;
            float t = tw[j << shift];
            float a = buf[idx1];
            float b = buf[idx1 + half];
            buf[idx1]        = fmaf(t, b, a);
            buf[idx1 + half] = fmaf(-t, b, a);
        }
        __syncthreads();
    }
    float* Xr = g_X + (size_t)row * 1024;
    for (int v = tid; v < 1024; v += 256) Xr[v] = buf[v];
}

// ---------------- 4: combine + transpose:  G[k][b*64+i] ----------------
__global__ void k_combine() {
    __shared__ float sa[64][33];
    __shared__ float sb[64][33];
    int k0 = blockIdx.x * 32;
    int b  = blockIdx.y;
    int tid = threadIdx.x;
    int kk = tid & 31, ii = tid >> 5;
    for (int i = ii; i < 64; i += 8) {
        sa[i][kk] = g_X[(size_t)(b * 64 + i) * 1024 + k0 + kk];
        sb[i][kk] = g_X[(size_t)((31 - b) * 64 + i) * 1024 + k0 + kk];
    }
    __syncthreads();
    int i2 = tid & 63, kq = tid >> 6;
    for (int kk2 = kq; kk2 < 32; kk2 += 4) {
        float v = 0.5f * (sa[i2][kk2] + sb[i2][kk2] + sa[63 - i2][kk2] - sb[63 - i2][kk2]);
        g_G[(size_t)(k0 + kk2) * 2048 + b * 64 + i2] = v;
    }
}

// ---------------- 5: weights (i,o,k) -> (k,i,o) ----------------
__global__ void k_wtrans(const float* __restrict__ w) {
    __shared__ float t[32][33];
    int k   = blockIdx.x * 32 + threadIdx.x;
    int io0 = blockIdx.y * 32;
    for (int j = threadIdx.y; j < 32; j += 8)
        t[j][threadIdx.x] = w[(size_t)(io0 + j) * 1024 + k];
    __syncthreads();
    int k0 = blockIdx.x * 32;
    for (int j = threadIdx.y; j < 32; j += 8)
        g_wT[(size_t)(k0 + j) * 4096 + io0 + threadIdx.x] = t[threadIdx.x][j];
}

// ---------------- 6: per-k mode mixing ----------------
__global__ void k_mix() {
    __shared__ float ws[4096];
    __shared__ float gs[2048];
    int k = blockIdx.x;
    int tid = threadIdx.x;
    const float* wk = g_wT + (size_t)k * 4096;
    const float* gk = g_G  + (size_t)k * 2048;
    for (int v = tid; v < 4096; v += 256) ws[v] = wk[v];
    for (int v = tid; v < 2048; v += 256) gs[v] = gk[v];
    __syncthreads();
    int o = tid & 63, bq = tid >> 6;
    float acc[8];
    #pragma unroll
    for (int r = 0; r < 8; r++) acc[r] = 0.0f;
    #pragma unroll 4
    for (int i = 0; i < 64; i++) {
        float wv = ws[i * 64 + o];
        #pragma unroll
        for (int r = 0; r < 8; r++)
            acc[r] = fmaf(gs[(bq + (r << 2)) * 64 + i], wv, acc[r]);
    }
    float* ok = g_out2 + (size_t)k * 2048;
    #pragma unroll
    for (int r = 0; r < 8; r++) ok[(bq + (r << 2)) * 64 + o] = acc[r];
}

// ---------------- 7: transpose + split A: out2 (k,m) fp32 -> Ahi/Alo (m,k) bf16 ----------------
__global__ void k_asplit() {
    __shared__ float t[32][33];
    int m0 = blockIdx.x * 32;
    int k0 = blockIdx.y * 32;
    int tx = threadIdx.x, ty = threadIdx.y;      // 32 x 8
    for (int j = ty; j < 32; j += 8)
        t[j][tx] = g_out2[(size_t)(k0 + j) * 2048 + m0 + tx];
    __syncthreads();
    for (int j = ty; j < 32; j += 8) {
        float v = t[tx][j];
        __nv_bfloat16 hi = __float2bfloat16_rn(v);
        __nv_bfloat16 lo = __float2bfloat16_rn(v - __bfloat162float(hi));
        size_t idx = (size_t)(m0 + j) * 1024 + k0 + tx;
        g_Ahi[idx] = hi;
        g_Alo[idx] = lo;
    }
}

// ---------------- 8: HMMA bf16-split GEMM (mma.sync, base sm_103 path) ----------------
// C[m][n] = sum_k (Ahi+Alo)[m][k]*(Bhi+Blo)[n][k], dropping lo*lo.
// 128x128 CTA tile, 8 warps (2x4), warp tile 64x32, K chunks of 32, cp.async 2-stage.
#define KC    32
#define AST   40                     // padded smem row stride (bf16 elems)
#define TILE_BYTES (128 * AST * 2)   // 10240
#define STAGE_BYTES (4 * TILE_BYTES) // 40960
#define HGEMM_SMEM  (2 * STAGE_BYTES)

__global__ __launch_bounds__(256, 1) void k_hgemm(float* __restrict__ C) {
    extern __shared__ __nv_bfloat16 sm[];
    const uint32_t smb = smem_u32(sm);
    const int tid = threadIdx.x;
    const int wid = tid >> 5, lane = tid & 31;
    const int wm = wid >> 2, wn = wid & 3;       // 2 x 4 warp grid
    const int m0 = blockIdx.y * 128, n0 = blockIdx.x * 128;

    const __nv_bfloat16* gb[4] = {
        g_Ahi + (size_t)m0 * 1024, g_Alo + (size_t)m0 * 1024,
        g_Bhi + (size_t)n0 * 1024, g_Blo + (size_t)n0 * 1024 };

    // per-thread load coords: 2 segments per tile per chunk
    const int seg0 = tid, seg1 = tid + 256;
    const int lr0 = seg0 >> 2, lc0 = (seg0 & 3) * 16;   // row, byte col within 64B of chunk
    const int lr1 = seg1 >> 2, lc1 = (seg1 & 3) * 16;

    float acc[4][4][4];
    #pragma unroll
    for (int i = 0; i < 4; i++)
        #pragma unroll
        for (int j = 0; j < 4; j++)
            #pragma unroll
            for (int q = 0; q < 4; q++) acc[i][j][q] = 0.0f;

    // issue chunk c into stage s
    auto issue = [&](int c, int s) {
        uint32_t sbase = smb + (uint32_t)s * STAGE_BYTES;
        size_t gc = (size_t)c * 64;              // byte offset along k
        #pragma unroll
        for (int t = 0; t < 4; t++) {
            const char* g = (const char*)gb[t];
            uint32_t tb = sbase + (uint32_t)t * TILE_BYTES;
            cp_async16(tb + (uint32_t)(lr0 * (AST * 2) + lc0), g + (size_t)lr0 * 2048 + gc + lc0);
            cp_async16(tb + (uint32_t)(lr1 * (AST * 2) + lc1), g + (size_t)lr1 * 2048 + gc + lc1);
        }
        asm volatile("cp.async.commit_group;" ::: "memory");
    };

    issue(0, 0);

    // ldmatrix per-lane offsets (bytes, within a tile)
    const uint32_t a_base = (uint32_t)(((wm * 64 + (lane & 15)) * AST + ((lane >> 4) << 3)) * 2);
    const uint32_t b_base = (uint32_t)(((wn * 32 + (lane & 7)) * AST + (((lane >> 3) & 1) << 3)) * 2);

    for (int c = 0; c < 32; ++c) {
        int s = c & 1;
        if (c + 1 < 32) {
            issue(c + 1, s ^ 1);
            asm volatile("cp.async.wait_group 1;" ::: "memory");
        } else {
            asm volatile("cp.async.wait_group 0;" ::: "memory");
        }
        __syncthreads();

        uint32_t st = smb + (uint32_t)s * STAGE_BYTES;
        #pragma unroll
        for (int kk = 0; kk < 2; ++kk) {         // two k16 steps
            uint32_t ko = (uint32_t)(kk * 32);   // 16 elems * 2B
            uint32_t ahi[4][4], alo[4][4], bhi[4][2], blo[4][2];
            #pragma unroll
            for (int mt = 0; mt < 4; ++mt) {
                uint32_t ao = a_base + ko + (uint32_t)(mt * 16 * AST * 2);
                ldm_x4(ahi[mt], st + ao);
                ldm_x4(alo[mt], st + TILE_BYTES + ao);
            }
            #pragma unroll
            for (int nt = 0; nt < 4; ++nt) {
                uint32_t bo = b_base + ko + (uint32_t)(nt * 8 * AST * 2);
                ldm_x2(bhi[nt], st + 2 * TILE_BYTES + bo);
                ldm_x2(blo[nt], st + 3 * TILE_BYTES + bo);
            }
            #pragma unroll
            for (int mt = 0; mt < 4; ++mt)
                #pragma unroll
                for (int nt = 0; nt < 4; ++nt) {
                    mma16816(acc[mt][nt], ahi[mt], bhi[nt]);
                    mma16816(acc[mt][nt], ahi[mt], blo[nt]);
                    mma16816(acc[mt][nt], alo[mt], bhi[nt]);
                }
        }
        __syncthreads();
    }

    // epilogue: m16n8 f32 fragment mapping
    const int rbase = m0 + wm * 64 + (lane >> 2);
    const int cbase = n0 + wn * 32 + (lane & 3) * 2;
    #pragma unroll
    for (int mt = 0; mt < 4; ++mt) {
        #pragma unroll
        for (int nt = 0; nt < 4; ++nt) {
            int r = rbase + mt * 16;
            int cc = cbase + nt * 8;
            if (cc < K2_)     C[(size_t)r * K2_ + cc]           = acc[mt][nt][0];
            if (cc + 1 < K2_) C[(size_t)r * K2_ + cc + 1]       = acc[mt][nt][1];
            if (cc < K2_)     C[(size_t)(r + 8) * K2_ + cc]     = acc[mt][nt][2];
            if (cc + 1 < K2_) C[(size_t)(r + 8) * K2_ + cc + 1] = acc[mt][nt][3];
        }
    }
}

// ---------------- launch ----------------
extern "C" void kernel_launch(void* const* d_in, const int* in_sizes, int n_in,
                              void* d_out, int out_size) {
    const float* x = (const float*)d_in[0];      // (32,64,4096)
    const float* w = (const float*)d_in[1];      // (64,64,1024)
    float* out = (float*)d_out;                  // (32,64,2049)

    cudaFuncSetAttribute(k_hgemm, cudaFuncAttributeMaxDynamicSharedMemorySize, HGEMM_SMEM);

    k_tables<<<16, 256>>>();
    k_casB<<<dim3(4, NB_), 256>>>();
    k_fht<<<2048, 256>>>(x);
    k_combine<<<dim3(32, 32), 256>>>();
    k_wtrans<<<dim3(32, 128), dim3(32, 8)>>>(w);
    k_mix<<<1024, 256>>>();
    k_asplit<<<dim3(64, 32), dim3(32, 8)>>>();
    k_hgemm<<<dim3(17, 16), 256, HGEMM_SMEM>>>(out);
}